// round 7
// baseline (speedup 1.0000x reference)
#include <cuda_runtime.h>

// Problem: B=2, 128^3 grid, C=3, 7 scaling-and-squaring steps.
#define D 128
#define DMASK 127
#define D3 (D * D * D)          // 2097152
#define NVOX (2 * D3)           // 4194304 voxels (B=2)

// Tile geometry: 8 x 8 x 32 voxels per block, halo +-3 (covers |disp| < 3;
// exact global-gather fallback for anything larger).
#define TX 8
#define TY 8
#define TZ 32
#define H  3
#define SX (TX + 2 * H)          // 14
#define SY (TY + 2 * H)          // 14
#define SZ (TZ + 2 * H)          // 38
#define SVOL (SX * SY * SZ)      // 7448
#define SMEM_BYTES (3 * SVOL * 4)  // 89376

#define TPB 512
#define NBLOCKS_TILE (2 * (D / TX) * (D / TY) * (D / TZ))  // 2048

// Two SoA ping-pong buffers, 48 MB each. Layout: [comp][b*D3 + x*D*D + y*D + z].
__device__ float gA[3 * NVOX];
__device__ float gB[3 * NVOX];

// ---------------------------------------------------------------------------
// Transpose + scale: AoS dvf (float3/voxel) -> SoA planes in gA, * 2^-7.
// ---------------------------------------------------------------------------
__global__ __launch_bounds__(256) void transpose_scale_kernel(
    const float4* __restrict__ in4)
{
    const int i = blockIdx.x * 256 + threadIdx.x;        // i < 3*NVOX/4
    const float s = 1.0f / 128.0f;                       // 2^-7, exact
    float4 v = in4[i];
    float vals[4] = {v.x, v.y, v.z, v.w};
    const int f = 4 * i;
    #pragma unroll
    for (int j = 0; j < 4; j++) {
        const int ff  = f + j;
        const int vox = ff / 3;
        const int c   = ff - 3 * vox;
        gA[c * NVOX + vox] = s * vals[j];
    }
}

// ---------------------------------------------------------------------------
// One squaring step with shared-memory tiling.
// SRC: 1 = gA, 2 = gB.   DST: 0 = external AoS, 1 = gA, 2 = gB.
// ---------------------------------------------------------------------------
template <int SRC, int DST>
__global__ __launch_bounds__(TPB, 2) void step_tile_kernel(
    float* __restrict__ ext_out)
{
    extern __shared__ float sm[];   // 3 planes of SVOL floats

    const float* __restrict__ px = (SRC == 1) ? gA : gB;
    const float* __restrict__ py = px + NVOX;
    const float* __restrict__ pz = px + 2 * NVOX;

    const int bid = blockIdx.x;
    const int tz0 = (bid & 3) * TZ;
    const int ty0 = ((bid >> 2) & 15) * TY;
    const int tx0 = ((bid >> 6) & 15) * TX;
    const int b   = bid >> 10;
    const int bbase = b * D3;

    const int xlo = tx0 - H, ylo = ty0 - H, zlo = tz0 - H;

    // ---- Cooperative halo load (clamped at volume edges) ----
    for (int i = threadIdx.x; i < SVOL; i += TPB) {
        const int sz = i % SZ;
        const int t  = i / SZ;
        const int sy = t % SY;
        const int sx = t / SY;
        const int gx = min(max(xlo + sx, 0), DMASK);
        const int gy = min(max(ylo + sy, 0), DMASK);
        const int gz = min(max(zlo + sz, 0), DMASK);
        const int lin = bbase + (gx << 14) + (gy << 7) + gz;
        sm[i]            = __ldg(px + lin);
        sm[SVOL + i]     = __ldg(py + lin);
        sm[2 * SVOL + i] = __ldg(pz + lin);
    }
    __syncthreads();

    const int lz = threadIdx.x & 31;
    const int ly = (threadIdx.x >> 5) & 7;
    const int xh = threadIdx.x >> 8;        // 0 or 1

    #pragma unroll
    for (int k = 0; k < 4; k++) {
        const int lx = xh + 2 * k;          // covers 0..7 across threads
        const int x = tx0 + lx, y = ty0 + ly, z = tz0 + lz;

        // Center displacement from smem (always inside the box).
        const int cs = ((lx + H) * SY + (ly + H)) * SZ + (lz + H);
        const float vx = sm[cs];
        const float vy = sm[SVOL + cs];
        const float vz = sm[2 * SVOL + cs];

        const float lxf = (float)x + vx;
        const float lyf = (float)y + vy;
        const float lzf = (float)z + vz;

        const float fx = floorf(lxf), fy = floorf(lyf), fz = floorf(lzf);
        const float wx1 = lxf - fx, wy1 = lyf - fy, wz1 = lzf - fz;
        const float wx0 = 1.0f - wx1, wy0 = 1.0f - wy1, wz0 = 1.0f - wz1;

        const int ix = (int)fx, iy = (int)fy, iz = (int)fz;

        // Clip corner indices; weights stay unclipped (matches reference).
        const int ix0 = min(max(ix,     0), DMASK);
        const int ix1 = min(max(ix + 1, 0), DMASK);
        const int iy0 = min(max(iy,     0), DMASK);
        const int iy1 = min(max(iy + 1, 0), DMASK);
        const int iz0 = min(max(iz,     0), DMASK);
        const int iz1 = min(max(iz + 1, 0), DMASK);

        const float w00 = wx0 * wy0;
        const float w01 = wx0 * wy1;
        const float w10 = wx1 * wy0;
        const float w11 = wx1 * wy1;
        const float w000 = w00 * wz0, w001 = w00 * wz1;
        const float w010 = w01 * wz0, w011 = w01 * wz1;
        const float w100 = w10 * wz0, w101 = w10 * wz1;
        const float w110 = w11 * wz0, w111 = w11 * wz1;

        float ax, ay, az;

        const bool inbox =
            (ix0 >= xlo) && (ix1 <= xlo + SX - 1) &&
            (iy0 >= ylo) && (iy1 <= ylo + SY - 1) &&
            (iz0 >= zlo) && (iz1 <= zlo + SZ - 1);

        if (inbox) {
            const int X0 = (ix0 - xlo) * (SY * SZ);
            const int X1 = (ix1 - xlo) * (SY * SZ);
            const int Y0 = (iy0 - ylo) * SZ;
            const int Y1 = (iy1 - ylo) * SZ;
            const int Z0 = iz0 - zlo;
            const int Z1 = iz1 - zlo;

            const int l000 = X0 + Y0 + Z0, l001 = X0 + Y0 + Z1;
            const int l010 = X0 + Y1 + Z0, l011 = X0 + Y1 + Z1;
            const int l100 = X1 + Y0 + Z0, l101 = X1 + Y0 + Z1;
            const int l110 = X1 + Y1 + Z0, l111 = X1 + Y1 + Z1;

            ax = w000 * sm[l000];            ay = w000 * sm[SVOL + l000];            az = w000 * sm[2*SVOL + l000];
            ax = fmaf(w001, sm[l001], ax);   ay = fmaf(w001, sm[SVOL + l001], ay);   az = fmaf(w001, sm[2*SVOL + l001], az);
            ax = fmaf(w010, sm[l010], ax);   ay = fmaf(w010, sm[SVOL + l010], ay);   az = fmaf(w010, sm[2*SVOL + l010], az);
            ax = fmaf(w011, sm[l011], ax);   ay = fmaf(w011, sm[SVOL + l011], ay);   az = fmaf(w011, sm[2*SVOL + l011], az);
            ax = fmaf(w100, sm[l100], ax);   ay = fmaf(w100, sm[SVOL + l100], ay);   az = fmaf(w100, sm[2*SVOL + l100], az);
            ax = fmaf(w101, sm[l101], ax);   ay = fmaf(w101, sm[SVOL + l101], ay);   az = fmaf(w101, sm[2*SVOL + l101], az);
            ax = fmaf(w110, sm[l110], ax);   ay = fmaf(w110, sm[SVOL + l110], ay);   az = fmaf(w110, sm[2*SVOL + l110], az);
            ax = fmaf(w111, sm[l111], ax);   ay = fmaf(w111, sm[SVOL + l111], ay);   az = fmaf(w111, sm[2*SVOL + l111], az);
        } else {
            // Rare exact fallback: gather from global planes.
            const int X0 = bbase + (ix0 << 14);
            const int X1 = bbase + (ix1 << 14);
            const int Y0 = iy0 << 7;
            const int Y1 = iy1 << 7;

            const int l000 = X0 + Y0 + iz0, l001 = X0 + Y0 + iz1;
            const int l010 = X0 + Y1 + iz0, l011 = X0 + Y1 + iz1;
            const int l100 = X1 + Y0 + iz0, l101 = X1 + Y0 + iz1;
            const int l110 = X1 + Y1 + iz0, l111 = X1 + Y1 + iz1;

            ax = w000 * __ldg(px + l000);          ay = w000 * __ldg(py + l000);          az = w000 * __ldg(pz + l000);
            ax = fmaf(w001, __ldg(px + l001), ax); ay = fmaf(w001, __ldg(py + l001), ay); az = fmaf(w001, __ldg(pz + l001), az);
            ax = fmaf(w010, __ldg(px + l010), ax); ay = fmaf(w010, __ldg(py + l010), ay); az = fmaf(w010, __ldg(pz + l010), az);
            ax = fmaf(w011, __ldg(px + l011), ax); ay = fmaf(w011, __ldg(py + l011), ay); az = fmaf(w011, __ldg(pz + l011), az);
            ax = fmaf(w100, __ldg(px + l100), ax); ay = fmaf(w100, __ldg(py + l100), ay); az = fmaf(w100, __ldg(pz + l100), az);
            ax = fmaf(w101, __ldg(px + l101), ax); ay = fmaf(w101, __ldg(py + l101), ay); az = fmaf(w101, __ldg(pz + l101), az);
            ax = fmaf(w110, __ldg(px + l110), ax); ay = fmaf(w110, __ldg(py + l110), ay); az = fmaf(w110, __ldg(pz + l110), az);
            ax = fmaf(w111, __ldg(px + l111), ax); ay = fmaf(w111, __ldg(py + l111), ay); az = fmaf(w111, __ldg(pz + l111), az);
        }

        const float ox = vx + ax;
        const float oy = vy + ay;
        const float oz = vz + az;

        const int idx = bbase + (x << 14) + (y << 7) + z;
        if (DST == 0) {
            float* o = ext_out + 3 * idx;
            o[0] = ox; o[1] = oy; o[2] = oz;
        } else {
            float* dx = (DST == 1) ? gA : gB;
            dx[idx]            = ox;
            dx[NVOX + idx]     = oy;
            dx[2 * NVOX + idx] = oz;
        }
    }
}

extern "C" void kernel_launch(void* const* d_in, const int* in_sizes, int n_in,
                              void* d_out, int out_size)
{
    const float4* dvf4 = (const float4*)d_in[0];
    float* out = (float*)d_out;

    cudaFuncSetAttribute(step_tile_kernel<1, 2>,
                         cudaFuncAttributeMaxDynamicSharedMemorySize, SMEM_BYTES);
    cudaFuncSetAttribute(step_tile_kernel<2, 1>,
                         cudaFuncAttributeMaxDynamicSharedMemorySize, SMEM_BYTES);
    cudaFuncSetAttribute(step_tile_kernel<1, 0>,
                         cudaFuncAttributeMaxDynamicSharedMemorySize, SMEM_BYTES);

    // AoS dvf -> scaled SoA in gA (ddf0 = dvf * 2^-7, exact).
    transpose_scale_kernel<<<(3 * NVOX / 4) / 256, 256>>>(dvf4);

    // 7 squaring steps, ping-pong; final step writes AoS into d_out.
    step_tile_kernel<1, 2><<<NBLOCKS_TILE, TPB, SMEM_BYTES>>>(nullptr);  // A -> B
    step_tile_kernel<2, 1><<<NBLOCKS_TILE, TPB, SMEM_BYTES>>>(nullptr);  // B -> A
    step_tile_kernel<1, 2><<<NBLOCKS_TILE, TPB, SMEM_BYTES>>>(nullptr);  // A -> B
    step_tile_kernel<2, 1><<<NBLOCKS_TILE, TPB, SMEM_BYTES>>>(nullptr);  // B -> A
    step_tile_kernel<1, 2><<<NBLOCKS_TILE, TPB, SMEM_BYTES>>>(nullptr);  // A -> B
    step_tile_kernel<2, 1><<<NBLOCKS_TILE, TPB, SMEM_BYTES>>>(nullptr);  // B -> A
    step_tile_kernel<1, 0><<<NBLOCKS_TILE, TPB, SMEM_BYTES>>>(out);      // A -> d_out
}

// round 8
// speedup vs baseline: 1.9563x; 1.9563x over previous
#include <cuda_runtime.h>

// Problem: B=2, 128^3 grid, C=3, 7 scaling-and-squaring steps.
#define D 128
#define DMASK 127
#define D3 (D * D * D)          // 2097152
#define NVOX (2 * D3)           // 4194304 voxels (B=2)
#define NT 128
#define NB (NVOX / NT)

// Two SoA ping-pong buffers, 48 MB each. Layout: [comp][b*D3 + x*D*D + y*D + z].
__device__ float gA[3 * NVOX];
__device__ float gB[3 * NVOX];

// ---------------------------------------------------------------------------
// Transpose + scale: AoS dvf (float3/voxel) -> SoA planes in gA, * 2^-7.
// ---------------------------------------------------------------------------
__global__ __launch_bounds__(256) void transpose_scale_kernel(
    const float4* __restrict__ in4)
{
    const int i = blockIdx.x * 256 + threadIdx.x;        // i < 3*NVOX/4
    const float s = 1.0f / 128.0f;                       // 2^-7, exact
    float4 v = in4[i];
    float vals[4] = {v.x, v.y, v.z, v.w};
    const int f = 4 * i;
    #pragma unroll
    for (int j = 0; j < 4; j++) {
        const int ff  = f + j;
        const int vox = ff / 3;
        const int c   = ff - 3 * vox;
        gA[c * NVOX + vox] = s * vals[j];
    }
}

// ---------------------------------------------------------------------------
// One squaring step, SoA -> SoA (or SoA -> AoS d_out on the last step).
// SRC: 1 = gA, 2 = gB.   DST: 0 = external AoS, 1 = gA, 2 = gB.
// Center loads first (they gate every gather address), then all index/weight
// ALU, then the gather+FMA stream (compiler-scheduled, ~32 regs).
// ---------------------------------------------------------------------------
template <int SRC, int DST>
__global__ __launch_bounds__(NT) void step_soa_kernel(
    float* __restrict__ ext_out)
{
    const float* __restrict__ sx = (SRC == 1) ? gA : gB;
    const float* __restrict__ sy = sx + NVOX;
    const float* __restrict__ sz = sx + 2 * NVOX;

    const int idx = blockIdx.x * NT + threadIdx.x;

    // Critical path first: center displacement (coalesced).
    const float vx = __ldg(sx + idx);
    const float vy = __ldg(sy + idx);
    const float vz = __ldg(sz + idx);

    const int z = idx & DMASK;
    const int y = (idx >> 7) & DMASK;
    const int x = (idx >> 14) & DMASK;
    const int bbase = (idx >> 21) * D3;

    const float lx = (float)x + vx;
    const float ly = (float)y + vy;
    const float lz = (float)z + vz;

    const float fx = floorf(lx), fy = floorf(ly), fz = floorf(lz);
    const float wx1 = lx - fx, wy1 = ly - fy, wz1 = lz - fz;
    const float wx0 = 1.0f - wx1, wy0 = 1.0f - wy1, wz0 = 1.0f - wz1;

    const int ix = (int)fx, iy = (int)fy, iz = (int)fz;

    // Clip corner indices; weights stay unclipped (matches reference).
    const int ix0 = min(max(ix,     0), DMASK);
    const int ix1 = min(max(ix + 1, 0), DMASK);
    const int iy0 = min(max(iy,     0), DMASK);
    const int iy1 = min(max(iy + 1, 0), DMASK);
    const int iz0 = min(max(iz,     0), DMASK);
    const int iz1 = min(max(iz + 1, 0), DMASK);

    const int X0 = bbase + (ix0 << 14);
    const int X1 = bbase + (ix1 << 14);
    const int Y0 = iy0 << 7;
    const int Y1 = iy1 << 7;

    const float w00 = wx0 * wy0;
    const float w01 = wx0 * wy1;
    const float w10 = wx1 * wy0;
    const float w11 = wx1 * wy1;

    float ax = 0.0f, ay = 0.0f, az = 0.0f;

    #define CORNER(W, LIN)                                                    \
        do {                                                                  \
            const float w_ = (W);                                             \
            const int   l_ = (LIN);                                           \
            ax = fmaf(w_, __ldg(sx + l_), ax);                                \
            ay = fmaf(w_, __ldg(sy + l_), ay);                                \
            az = fmaf(w_, __ldg(sz + l_), az);                                \
        } while (0)

    CORNER(w00 * wz0, X0 + Y0 + iz0);
    CORNER(w00 * wz1, X0 + Y0 + iz1);
    CORNER(w01 * wz0, X0 + Y1 + iz0);
    CORNER(w01 * wz1, X0 + Y1 + iz1);
    CORNER(w10 * wz0, X1 + Y0 + iz0);
    CORNER(w10 * wz1, X1 + Y0 + iz1);
    CORNER(w11 * wz0, X1 + Y1 + iz0);
    CORNER(w11 * wz1, X1 + Y1 + iz1);
    #undef CORNER

    const float ox = vx + ax;
    const float oy = vy + ay;
    const float oz = vz + az;

    if (DST == 0) {
        // Final step: AoS float3 into d_out.
        float* o = ext_out + 3 * idx;
        o[0] = ox; o[1] = oy; o[2] = oz;
    } else {
        float* dx = (DST == 1) ? gA : gB;
        dx[idx]            = ox;
        dx[NVOX + idx]     = oy;
        dx[2 * NVOX + idx] = oz;
    }
}

extern "C" void kernel_launch(void* const* d_in, const int* in_sizes, int n_in,
                              void* d_out, int out_size)
{
    const float4* dvf4 = (const float4*)d_in[0];
    float* out = (float*)d_out;

    // AoS dvf -> scaled SoA in gA (ddf0 = dvf * 2^-7, exact).
    transpose_scale_kernel<<<(3 * NVOX / 4) / 256, 256>>>(dvf4);

    // 7 squaring steps, ping-pong; final step writes AoS into d_out.
    step_soa_kernel<1, 2><<<NB, NT>>>(nullptr);  // 1: A -> B
    step_soa_kernel<2, 1><<<NB, NT>>>(nullptr);  // 2: B -> A
    step_soa_kernel<1, 2><<<NB, NT>>>(nullptr);  // 3: A -> B
    step_soa_kernel<2, 1><<<NB, NT>>>(nullptr);  // 4: B -> A
    step_soa_kernel<1, 2><<<NB, NT>>>(nullptr);  // 5: A -> B
    step_soa_kernel<2, 1><<<NB, NT>>>(nullptr);  // 6: B -> A
    step_soa_kernel<1, 0><<<NB, NT>>>(out);      // 7: A -> d_out
}